// round 2
// baseline (speedup 1.0000x reference)
#include <cuda_runtime.h>
#include <math.h>

#define FEAT 128
#define NRBF 20
#define NGRAPHS 128
#define ATOMS 64
#define NATOMS (NGRAPHS * ATOMS)
#define NEDGES (NATOMS * 32)

__device__ __align__(16) float g_H[NATOMS * FEAT];
__device__ __align__(16) float g_phi[NATOMS * 3 * FEAT];
__device__ __align__(16) float g_qkv[NATOMS * 3 * FEAT];
__device__ __align__(16) float g_scratch[NATOMS * FEAT * 4];

__global__ void zero_scratch_kernel() {
    int idx = blockIdx.x * blockDim.x + threadIdx.x;
    float4 z = make_float4(0.f, 0.f, 0.f, 0.f);
    reinterpret_cast<float4*>(g_scratch)[idx] = z;
}

// C[M,N] = act(A[M,128] @ W[128,N] + bias), row-major. Tile 64x64, 256 threads.
template <int ACT>
__global__ void gemm64_kernel(const float* __restrict__ A, const float* __restrict__ W,
                              const float* __restrict__ bias, float* __restrict__ C, int N) {
    __shared__ float As[64][65];   // As[k][m], padded
    __shared__ float Ws[64][64];   // Ws[k][n]
    int t = threadIdx.x;
    int tx = t & 15, ty = t >> 4;
    int m_blk = blockIdx.y * 64;
    int n_blk = blockIdx.x * 64;

    float acc[4][4];
#pragma unroll
    for (int i = 0; i < 4; i++)
#pragma unroll
        for (int j = 0; j < 4; j++) acc[i][j] = 0.f;

    for (int k0 = 0; k0 < 128; k0 += 64) {
        // Load A tile (64 rows x 64 k), store transposed
        {
            int r = t >> 2;            // 0..63
            int c4b = (t & 3) * 4;     // base float4 idx (16 per row)
            const float4* src = reinterpret_cast<const float4*>(A + (size_t)(m_blk + r) * 128 + k0);
#pragma unroll
            for (int i = 0; i < 4; i++) {
                float4 v = src[c4b + i];
                int kk = (c4b + i) * 4;
                As[kk + 0][r] = v.x; As[kk + 1][r] = v.y;
                As[kk + 2][r] = v.z; As[kk + 3][r] = v.w;
            }
            // Load W tile (64 k x 64 n)
            const float4* wsrc = reinterpret_cast<const float4*>(W + (size_t)(k0 + r) * N + n_blk);
            float4* wdst = reinterpret_cast<float4*>(&Ws[r][0]);
#pragma unroll
            for (int i = 0; i < 4; i++) wdst[c4b + i] = wsrc[c4b + i];
        }
        __syncthreads();
#pragma unroll
        for (int k = 0; k < 64; k++) {
            float a0 = As[k][ty * 4 + 0];
            float a1 = As[k][ty * 4 + 1];
            float a2 = As[k][ty * 4 + 2];
            float a3 = As[k][ty * 4 + 3];
            float4 w = *reinterpret_cast<const float4*>(&Ws[k][tx * 4]);
            acc[0][0] += a0 * w.x; acc[0][1] += a0 * w.y; acc[0][2] += a0 * w.z; acc[0][3] += a0 * w.w;
            acc[1][0] += a1 * w.x; acc[1][1] += a1 * w.y; acc[1][2] += a1 * w.z; acc[1][3] += a1 * w.w;
            acc[2][0] += a2 * w.x; acc[2][1] += a2 * w.y; acc[2][2] += a2 * w.z; acc[2][3] += a2 * w.w;
            acc[3][0] += a3 * w.x; acc[3][1] += a3 * w.y; acc[3][2] += a3 * w.z; acc[3][3] += a3 * w.w;
        }
        __syncthreads();
    }
#pragma unroll
    for (int i = 0; i < 4; i++) {
        int m = m_blk + ty * 4 + i;
#pragma unroll
        for (int j = 0; j < 4; j++) {
            int n = n_blk + tx * 4 + j;
            float v = acc[i][j] + bias[n];
            if (ACT) v = v / (1.0f + expf(-v));   // silu
            C[(size_t)m * N + n] = v;
        }
    }
}

// Per-edge message: thread f owns features (f, f+128, f+256). Wr columns in registers.
__global__ void edge_kernel(const float* __restrict__ phi, const float* __restrict__ v_j,
                            const float* __restrict__ r_ij, const int* __restrict__ nbrs,
                            const float* __restrict__ Wr, const float* __restrict__ br) {
    const float PI = 3.14159265358979323846f;
    const float CUTOFF = 5.0f;
    int f = threadIdx.x;

    float wr0[NRBF], wr1[NRBF], wr2[NRBF];
#pragma unroll
    for (int n = 0; n < NRBF; n++) {
        wr0[n] = Wr[n * 384 + f];
        wr1[n] = Wr[n * 384 + 128 + f];
        wr2[n] = Wr[n * 384 + 256 + f];
    }
    float br0 = br[f], br1 = br[128 + f], br2 = br[256 + f];

    for (int e = blockIdx.x; e < NEDGES; e += gridDim.x) {
        float rx = r_ij[3 * e + 0];
        float ry = r_ij[3 * e + 1];
        float rz = r_ij[3 * e + 2];
        float d2 = rx * rx + ry * ry + rz * rz;
        float d = sqrtf(d2);
        if (d >= CUTOFF) continue;   // env == 0 -> zero contribution

        int i = nbrs[2 * e + 0];
        int j = nbrs[2 * e + 1];
        float invd = 1.0f / d;
        float theta = d * (PI / CUTOFF);
        float sv = __sinf(theta);
        float cv = __cosf(theta);
        float env = 0.5f * (cv + 1.0f);
        float two_c = 2.0f * cv;

        // rbf dot via Chebyshev recurrence: sin((n+1)t) = 2cos(t) sin(nt) - sin((n-1)t)
        float S0 = 0.f, S1 = 0.f, S2 = 0.f;
        float sp = sv, spp = 0.f;
#pragma unroll
        for (int n = 0; n < NRBF; n++) {
            S0 += sp * wr0[n];
            S1 += sp * wr1[n];
            S2 += sp * wr2[n];
            float sn = two_c * sp - spp;
            spp = sp;
            sp = sn;
        }
        float w0 = (S0 * invd + br0) * env;
        float w1 = (S1 * invd + br1) * env;
        float w2 = (S2 * invd + br2) * env;

        const float* ph = phi + (size_t)j * 384;
        float a0 = ph[f] * w0;
        float a1 = ph[128 + f] * w1;
        float a2 = ph[256 + f] * w2;

        float ux = rx * invd, uy = ry * invd, uz = rz * invd;
        const float* vj = v_j + ((size_t)j * 128 + f) * 3;
        float dv0 = a2 * ux + a0 * vj[0];
        float dv1 = a2 * uy + a0 * vj[1];
        float dv2 = a2 * uz + a0 * vj[2];

        float* dst = g_scratch + ((size_t)i * 128 + f) * 4;
        asm volatile("red.global.add.v4.f32 [%0], {%1, %2, %3, %4};"
                     :: "l"(dst), "f"(a1), "f"(dv0), "f"(dv1), "f"(dv2)
                     : "memory");
    }
}

// One graph per block: 64x64 attention over FEAT=128. Static smem = 48KB exactly.
__global__ void attn_kernel(const float* __restrict__ qkv) {
    __shared__ float Qs[FEAT][ATOMS];   // transposed Q: [128][64] = 32KB
    __shared__ float S[ATOMS][ATOMS];   // S[k][q] = 16KB
    int g = blockIdx.x;
    int t = threadIdx.x;  // 128
    const float* base = qkv + (size_t)g * ATOMS * 384;

    {   // load Q transposed
        int q = t >> 1;
        int fb = (t & 1) * 64;
        const float4* src = reinterpret_cast<const float4*>(base + (size_t)q * 384 + fb);
#pragma unroll
        for (int i = 0; i < 16; i++) {
            float4 v = src[i];
            int ff = fb + i * 4;
            Qs[ff + 0][q] = v.x; Qs[ff + 1][q] = v.y;
            Qs[ff + 2][q] = v.z; Qs[ff + 3][q] = v.w;
        }
    }
    __syncthreads();

    {   // scores
        int q = t & 63;
        int k0 = (t >> 6) * 32;
        for (int kk = 0; kk < 32; kk++) {
            int k = k0 + kk;
            const float4* Krow = reinterpret_cast<const float4*>(base + (size_t)k * 384 + 128);
            float s = 0.f;
#pragma unroll
            for (int i = 0; i < 32; i++) {
                float4 kv = Krow[i];
                int ff = i * 4;
                s += Qs[ff + 0][q] * kv.x + Qs[ff + 1][q] * kv.y
                   + Qs[ff + 2][q] * kv.z + Qs[ff + 3][q] * kv.w;
            }
            S[k][q] = s * 0.08838834764831845f;  // 1/sqrt(128)
        }
    }
    __syncthreads();

    if (t < 64) {   // softmax over k per q column
        int q = t;
        float m = -1e30f;
        for (int k = 0; k < 64; k++) m = fmaxf(m, S[k][q]);
        float sum = 0.f;
        for (int k = 0; k < 64; k++) {
            float e = expf(S[k][q] - m);
            S[k][q] = e;
            sum += e;
        }
        float inv = 1.0f / sum;
        for (int k = 0; k < 64; k++) S[k][q] *= inv;
    }
    __syncthreads();

    {   // att = P @ V, accumulate into scratch s-slot
        int q = t >> 1;
        int fb = (t & 1) * 64;
        float acc[64];
#pragma unroll
        for (int i = 0; i < 64; i++) acc[i] = 0.f;
        for (int k = 0; k < 64; k++) {
            float p = S[k][q];
            const float4* Vrow = reinterpret_cast<const float4*>(base + (size_t)k * 384 + 256 + fb);
#pragma unroll
            for (int i = 0; i < 16; i++) {
                float4 v = Vrow[i];
                acc[i * 4 + 0] += p * v.x; acc[i * 4 + 1] += p * v.y;
                acc[i * 4 + 2] += p * v.z; acc[i * 4 + 3] += p * v.w;
            }
        }
        int atom = g * ATOMS + q;
        float* dst = g_scratch + ((size_t)atom * 128 + fb) * 4;
#pragma unroll
        for (int i = 0; i < 64; i++) dst[i * 4] += acc[i];   // exclusive after edge kernel
    }
}

// De-interleave scratch -> d_out: [delta_s (NATOMS*128)] then [delta_v (NATOMS*128*3)]
__global__ void finalize_kernel(float* __restrict__ out) {
    int idx = blockIdx.x * blockDim.x + threadIdx.x;  // 0 .. NATOMS*FEAT-1
    float4 v = reinterpret_cast<const float4*>(g_scratch)[idx];
    out[idx] = v.x;
    float* ov = out + (size_t)NATOMS * FEAT + (size_t)idx * 3;
    ov[0] = v.y;
    ov[1] = v.z;
    ov[2] = v.w;
}

extern "C" void kernel_launch(void* const* d_in, const int* in_sizes, int n_in,
                              void* d_out, int out_size) {
    const float* s_j  = (const float*)d_in[0];
    const float* v_j  = (const float*)d_in[1];
    const float* r_ij = (const float*)d_in[2];
    const int*   nbrs = (const int*)d_in[3];
    // d_in[4] = num_atoms (unused; all graphs full)
    const float* W1 = (const float*)d_in[5];
    const float* b1 = (const float*)d_in[6];
    const float* W2 = (const float*)d_in[7];
    const float* b2 = (const float*)d_in[8];
    const float* Wr = (const float*)d_in[9];
    const float* br = (const float*)d_in[10];
    const float* Wd = (const float*)d_in[11];
    const float* bd = (const float*)d_in[12];
    float* out = (float*)d_out;

    float *pH, *pPhi, *pQkv;
    cudaGetSymbolAddress((void**)&pH, g_H);
    cudaGetSymbolAddress((void**)&pPhi, g_phi);
    cudaGetSymbolAddress((void**)&pQkv, g_qkv);

    zero_scratch_kernel<<<(NATOMS * FEAT) / 256, 256>>>();

    dim3 g1(FEAT / 64, NATOMS / 64);       // (2, 128)
    gemm64_kernel<1><<<g1, 256>>>(s_j, W1, b1, pH, 128);
    dim3 g2((3 * FEAT) / 64, NATOMS / 64); // (6, 128)
    gemm64_kernel<0><<<g2, 256>>>(pH, W2, b2, pPhi, 384);
    gemm64_kernel<0><<<g2, 256>>>(s_j, Wd, bd, pQkv, 384);

    edge_kernel<<<2048, 128>>>(pPhi, v_j, r_ij, nbrs, Wr, br);
    attn_kernel<<<NGRAPHS, 128>>>(pQkv);
    finalize_kernel<<<(NATOMS * FEAT) / 256, 256>>>(out);
}